// round 8
// baseline (speedup 1.0000x reference)
#include <cuda_runtime.h>
#include <cuda_fp16.h>
#include <cstdint>

// ============================================================
// out = diag(1/(rowsum(adj)+beta)) @ (adj + diag(beta)) @ x @ W + bias
// R7->R8:
//  * kernel B: MT 64->32, smem 131->78KB => 2 CTAs/SM (was 1; latency-bound
//    at occ 25%). B-frags now ldmatrix.trans from row-major g_yh[k][n].
//  * kernel A: tensorized (fp16 HMMA, W-frags via ldmatrix.trans); no
//    transposed copy of y needed anymore.
// ============================================================

#define NN 8192
#define FF 256
#define MT 32             // CTA M tile (kernel B)
#define KS 64             // K per stage
#define NITER (NN / KS)   // 128
#define KSPA 72           // A row stride in halves (144B)
#define KSPB 264          // B row stride in halves (528B): 8-row ldm conflict-free
#define AS_STAGE (MT * KSPA)        // 2304 halves
#define AS_STAGE_B (AS_STAGE * 2)   // 4608 B
#define BS_STAGE (KS * KSPB)        // 16896 halves
#define BS_STAGE_B (BS_STAGE * 2)   // 33792 B

#define OFF_BIAS  0      // 256 f32
#define OFF_RS    1024   // 32 f32
#define OFF_SCALE 1152
#define OFF_BETA  1280
#define OFF_AS    1536                        // 2 stages * 4608
#define OFF_BS    (OFF_AS + 2 * AS_STAGE_B)   // 10752, 2 stages * 33792
#define SMEM_TOTAL (OFF_BS + 2 * BS_STAGE_B)  // 78336  (x2 CTAs = 156672/SM)

__device__ __align__(256) float  g_y[NN * FF];   // y [node][feat] fp32
__device__ __align__(256) __half g_yh[NN * FF];  // y [node][feat] fp16 (row-major!)

// ---------------- helpers ----------------
__device__ __forceinline__ uint32_t smem_u32(const void* p) {
    uint32_t a;
    asm("{ .reg .u64 t; cvta.to.shared.u64 t, %1; cvt.u32.u64 %0, t; }" : "=r"(a) : "l"(p));
    return a;
}
__device__ __forceinline__ void cp16(uint32_t dst, const void* src) {
    asm volatile("cp.async.cg.shared.global [%0], [%1], 16;" :: "r"(dst), "l"(src));
}
__device__ __forceinline__ void cp_commit() {
    asm volatile("cp.async.commit_group;" ::: "memory");
}
__device__ __forceinline__ void ldm_x4(uint32_t* r, uint32_t addr) {
    asm volatile("ldmatrix.sync.aligned.m8n8.x4.shared.b16 {%0,%1,%2,%3}, [%4];"
        : "=r"(r[0]), "=r"(r[1]), "=r"(r[2]), "=r"(r[3]) : "r"(addr));
}
__device__ __forceinline__ void ldm_x4_t(uint32_t* r, uint32_t addr) {
    asm volatile("ldmatrix.sync.aligned.m8n8.x4.trans.shared.b16 {%0,%1,%2,%3}, [%4];"
        : "=r"(r[0]), "=r"(r[1]), "=r"(r[2]), "=r"(r[3]) : "r"(addr));
}
__device__ __forceinline__ void mma_f16(float* c, const uint32_t* a, uint32_t b0, uint32_t b1) {
    asm volatile(
        "mma.sync.aligned.m16n8k16.row.col.f32.f16.f16.f32 "
        "{%0,%1,%2,%3}, {%4,%5,%6,%7}, {%8,%9}, {%0,%1,%2,%3};"
        : "+f"(c[0]), "+f"(c[1]), "+f"(c[2]), "+f"(c[3])
        : "r"(a[0]), "r"(a[1]), "r"(a[2]), "r"(a[3]), "r"(b0), "r"(b1));
}

// ---------------- kernel A: y = x @ W (fp16 HMMA), writes g_y + g_yh ----------------
// MT_A=64, N=256, 512 thr (16 warps, 2m x 8n, warp tile 32x32), K chunks of 64.
__global__ void __launch_bounds__(512) gemm_y_kernel(const float* __restrict__ x,
                                                     const float* __restrict__ w)
{
    __shared__ __half xs[64 * KSPA];    // [m][k] chunk
    __shared__ __half ws[64 * KSPB];    // [k][n] chunk (trans-ldm as B)
    const int tid = threadIdx.x;
    const int wid = tid >> 5, lane = tid & 31;
    const int g = lane >> 2, t = lane & 3;
    const int wm = wid & 1, wn = wid >> 1;
    const int m0 = blockIdx.x * 64;
    const int mt8 = lane >> 3, r8 = lane & 7;

    const uint32_t a_lm = smem_u32(xs) +
        (((wm * 32 + (mt8 & 1) * 8 + r8) * KSPA + (mt8 >> 1) * 8) * 2);
    const uint32_t b_lm = smem_u32(ws) +
        (((r8 + (mt8 & 1) * 8) * KSPB + wn * 32 + (lane >> 4) * 8) * 2);

    float acc[2][4][4];
    #pragma unroll
    for (int i = 0; i < 2; i++)
        #pragma unroll
        for (int j = 0; j < 4; j++)
            #pragma unroll
            for (int q = 0; q < 4; q++) acc[i][j][q] = 0.f;

    const int xr = tid >> 3, xq = tid & 7;       // x: row, 8-float chunk
    for (int c = 0; c < 4; c++) {
        const int k0 = c * 64;
        {   // stage x chunk [64m][64k] fp32 -> fp16
            const float4 v0 = *(const float4*)&x[(size_t)(m0 + xr) * FF + k0 + xq * 8];
            const float4 v1 = *(const float4*)&x[(size_t)(m0 + xr) * FF + k0 + xq * 8 + 4];
            __half2 h[4];
            h[0] = __floats2half2_rn(v0.x, v0.y); h[1] = __floats2half2_rn(v0.z, v0.w);
            h[2] = __floats2half2_rn(v1.x, v1.y); h[3] = __floats2half2_rn(v1.z, v1.w);
            *(uint4*)&xs[xr * KSPA + xq * 8] = make_uint4(
                *(uint32_t*)&h[0], *(uint32_t*)&h[1], *(uint32_t*)&h[2], *(uint32_t*)&h[3]);
        }
        {   // stage W chunk [64k][256n] fp32 -> fp16
            #pragma unroll
            for (int j2 = 0; j2 < 4; j2++) {
                const float4 u0 = *(const float4*)&w[(size_t)(k0 + xr) * FF + xq * 32 + j2 * 8];
                const float4 u1 = *(const float4*)&w[(size_t)(k0 + xr) * FF + xq * 32 + j2 * 8 + 4];
                __half2 h[4];
                h[0] = __floats2half2_rn(u0.x, u0.y); h[1] = __floats2half2_rn(u0.z, u0.w);
                h[2] = __floats2half2_rn(u1.x, u1.y); h[3] = __floats2half2_rn(u1.z, u1.w);
                *(uint4*)&ws[xr * KSPB + xq * 32 + j2 * 8] = make_uint4(
                    *(uint32_t*)&h[0], *(uint32_t*)&h[1], *(uint32_t*)&h[2], *(uint32_t*)&h[3]);
            }
        }
        __syncthreads();
        #pragma unroll
        for (int kk = 0; kk < 4; kk++) {
            uint32_t a0[4], a1[4];
            ldm_x4(a0, a_lm + kk * 32);
            ldm_x4(a1, a_lm + kk * 32 + 16 * KSPA * 2);
            uint32_t bf[2][4];
            #pragma unroll
            for (int p = 0; p < 2; p++)
                ldm_x4_t(bf[p], b_lm + (uint32_t)(kk * 16 * KSPB + p * 16) * 2);
            #pragma unroll
            for (int p = 0; p < 2; p++) {
                mma_f16(acc[0][2 * p],     a0, bf[p][0], bf[p][1]);
                mma_f16(acc[1][2 * p],     a1, bf[p][0], bf[p][1]);
                mma_f16(acc[0][2 * p + 1], a0, bf[p][2], bf[p][3]);
                mma_f16(acc[1][2 * p + 1], a1, bf[p][2], bf[p][3]);
            }
        }
        __syncthreads();
    }

    // epilogue: write fp32 g_y and fp16 g_yh (both row-major [m][n])
    #pragma unroll
    for (int mi = 0; mi < 2; mi++) {
        const int lm = wm * 32 + mi * 16 + g;
        #pragma unroll
        for (int nj = 0; nj < 4; nj++) {
            const int n = wn * 32 + nj * 8 + 2 * t;
            const float* cc = acc[mi][nj];
            const size_t b0 = (size_t)(m0 + lm) * FF + n;
            const size_t b1 = (size_t)(m0 + lm + 8) * FF + n;
            *(float2*)&g_y[b0] = make_float2(cc[0], cc[1]);
            *(float2*)&g_y[b1] = make_float2(cc[2], cc[3]);
            __half2 h0 = __floats2half2_rn(cc[0], cc[1]);
            __half2 h1 = __floats2half2_rn(cc[2], cc[3]);
            *(__half2*)&g_yh[b0] = h0;
            *(__half2*)&g_yh[b1] = h1;
        }
    }
}

// ---------------- kernel B: C = adj @ y + fused epilogue ----------------
__global__ void __launch_bounds__(512, 2) gcn_mma_kernel(
    const float* __restrict__ adj,
    const float* __restrict__ beta,
    const float* __restrict__ bias,
    float* __restrict__ out)
{
    extern __shared__ char smem[];
    float* bias_s  = (float*)(smem + OFF_BIAS);
    float* rs_s    = (float*)(smem + OFF_RS);
    float* scale_s = (float*)(smem + OFF_SCALE);
    float* beta_s  = (float*)(smem + OFF_BETA);
    __half* As     = (__half*)(smem + OFF_AS);
    const uint32_t sb = smem_u32(smem);

    const int tid = threadIdx.x;
    const int wid = tid >> 5, lane = tid & 31;
    const int g = lane >> 2, t = lane & 3;
    const int wm = wid & 1, wn = wid >> 1;     // 2 m-warps x 8 n-warps (tile 16x32)
    const int m0 = blockIdx.x * MT;

    if (tid < FF) bias_s[tid] = bias[tid];

    // A: 16 threads per row, 4 floats each
    const int ar = tid >> 4, acq = tid & 15;
    const float* aptr = adj + (size_t)(m0 + ar) * NN + acq * 4;
    __half* const a_st = As + ar * KSPA + acq * 4;      // generic ptr for STS
    // B: row-major g_yh[k][n]; 8 threads per k-row, 32 halves each
    const int br = tid >> 3, bq = tid & 7;
    const __half* bptr = g_yh + (size_t)br * FF + bq * 32;
    const uint32_t b_dst = sb + OFF_BS + (br * KSPB + bq * 32) * 2;

    // ldmatrix lane addresses
    const int mt8 = lane >> 3, r8 = lane & 7;
    const uint32_t a_lm = sb + OFF_AS +
        (((wm * 16 + (mt8 & 1) * 8 + r8) * KSPA + (mt8 >> 1) * 8) * 2);
    const uint32_t b_lm = sb + OFF_BS +
        (((r8 + (mt8 & 1) * 8) * KSPB + wn * 32 + (lane >> 4) * 8) * 2);

    float rs_local = 0.f;
    float acc[4][4];
    #pragma unroll
    for (int j = 0; j < 4; j++)
        #pragma unroll
        for (int q = 0; q < 4; q++) acc[j][q] = 0.f;

    float4 ra[2];

    // ---- prologue ----
    #pragma unroll
    for (int s = 0; s < 2; s++) {
        const __half* bp = bptr + (size_t)s * KS * FF;
        #pragma unroll
        for (int q = 0; q < 4; q++)
            cp16(b_dst + s * BS_STAGE_B + q * 16, (const void*)(bp + q * 8));
        cp_commit();
    }
    ra[0] = *(const float4*)(aptr);
    ra[1] = *(const float4*)(aptr + KS);
    {   // STS A stage 0 + rowsum
        const float4 v = ra[0];
        rs_local += v.x + v.y + v.z + v.w;
        __half2 h0 = __floats2half2_rn(v.x, v.y), h1 = __floats2half2_rn(v.z, v.w);
        *(uint2*)a_st = make_uint2(*(uint32_t*)&h0, *(uint32_t*)&h1);
    }

    // ---- main loop ----
    for (int i = 0; i < NITER; i++) {
        if (i + 2 < NITER)
            ra[i & 1] = *(const float4*)(aptr + (size_t)(i + 2) * KS);

        if (i < NITER - 1) { asm volatile("cp.async.wait_group 1;" ::: "memory"); }
        else               { asm volatile("cp.async.wait_group 0;" ::: "memory"); }
        __syncthreads();

        if (i + 1 < NITER) {     // STS A stage i+1 + rowsum
            const float4 v = ra[(i + 1) & 1];
            rs_local += v.x + v.y + v.z + v.w;
            __half2 h0 = __floats2half2_rn(v.x, v.y), h1 = __floats2half2_rn(v.z, v.w);
            *(uint2*)(a_st + ((i + 1) & 1) * AS_STAGE) =
                make_uint2(*(uint32_t*)&h0, *(uint32_t*)&h1);
        }

        // ---- compute stage i ----
        const uint32_t aB = a_lm + (i & 1) * AS_STAGE_B;
        const uint32_t bB = b_lm + (i & 1) * BS_STAGE_B;
        #pragma unroll
        for (int kk = 0; kk < 4; kk++) {
            uint32_t a[4];
            ldm_x4(a, aB + kk * 32);
            uint32_t bf0[4], bf1[4];
            ldm_x4_t(bf0, bB + (uint32_t)(kk * 16 * KSPB) * 2);
            ldm_x4_t(bf1, bB + (uint32_t)(kk * 16 * KSPB) * 2 + 32);
            mma_f16(acc[0], a, bf0[0], bf0[1]);
            mma_f16(acc[1], a, bf0[2], bf0[3]);
            mma_f16(acc[2], a, bf1[0], bf1[1]);
            mma_f16(acc[3], a, bf1[2], bf1[3]);
        }
        __syncthreads();    // everyone done with B buf (i&1) before overwrite

        if (i + 2 < NITER) {     // cp.async B stage i+2 into buf (i&1)
            const uint32_t bd = b_dst + (i & 1) * BS_STAGE_B;
            const __half* bp = bptr + (size_t)(i + 2) * KS * FF;
            #pragma unroll
            for (int q = 0; q < 4; q++) cp16(bd + q * 16, (const void*)(bp + q * 8));
            cp_commit();
        }
    }

    // ---- rowsum reduce (16 threads per row) ----
    float rs = rs_local;
    rs += __shfl_xor_sync(0xffffffffu, rs, 1);
    rs += __shfl_xor_sync(0xffffffffu, rs, 2);
    rs += __shfl_xor_sync(0xffffffffu, rs, 4);
    rs += __shfl_xor_sync(0xffffffffu, rs, 8);
    if ((tid & 15) == 0) rs_s[ar] = rs;
    __syncthreads();
    if (tid < MT) {
        const float be = beta[m0 + tid];
        beta_s[tid] = be;
        scale_s[tid] = 1.0f / (rs_s[tid] + be);
    }
    __syncthreads();

    // ---- epilogue: out = scale*(C + beta*y) + bias ----
    const int lm = wm * 16 + g;
    const float sc0 = scale_s[lm],     be0 = beta_s[lm];
    const float sc1 = scale_s[lm + 8], be1 = beta_s[lm + 8];
    #pragma unroll
    for (int nj = 0; nj < 4; nj++) {
        const int n = wn * 32 + nj * 8 + 2 * t;
        const size_t base0 = (size_t)(m0 + lm) * FF + n;
        const size_t base1 = (size_t)(m0 + lm + 8) * FF + n;
        const float2 y0 = *(const float2*)&g_y[base0];
        const float2 y1 = *(const float2*)&g_y[base1];
        float2 o0, o1;
        o0.x = sc0 * (acc[nj][0] + be0 * y0.x) + bias_s[n];
        o0.y = sc0 * (acc[nj][1] + be0 * y0.y) + bias_s[n + 1];
        o1.x = sc1 * (acc[nj][2] + be1 * y1.x) + bias_s[n];
        o1.y = sc1 * (acc[nj][3] + be1 * y1.y) + bias_s[n + 1];
        *(float2*)&out[base0] = o0;
        *(float2*)&out[base1] = o1;
    }
}

// ---------------- launch ----------------
extern "C" void kernel_launch(void* const* d_in, const int* in_sizes, int n_in,
                              void* d_out, int out_size)
{
    const float *x = nullptr, *adj = nullptr, *w = nullptr, *bias = nullptr, *beta = nullptr;
    for (int i = 0; i < n_in; i++) {
        switch (in_sizes[i]) {
            case NN * FF:   x    = (const float*)d_in[i]; break;
            case 67108864:  adj  = (const float*)d_in[i]; break;
            case FF * FF:   w    = (const float*)d_in[i]; break;
            case FF:        bias = (const float*)d_in[i]; break;
            case NN:        beta = (const float*)d_in[i]; break;
            default: break;
        }
    }
    float* out = (float*)d_out;

    cudaFuncSetAttribute(gcn_mma_kernel, cudaFuncAttributeMaxDynamicSharedMemorySize, SMEM_TOTAL);

    gemm_y_kernel<<<NN / 64, 512>>>(x, w);
    gcn_mma_kernel<<<NN / MT, 512, SMEM_TOTAL>>>(adj, beta, bias, out);
}

// round 9
// speedup vs baseline: 1.7643x; 1.7643x over previous
#include <cuda_runtime.h>
#include <cuda_fp16.h>
#include <cstdint>

// ============================================================
// out = diag(1/(rowsum(adj)+beta)) @ (adj + diag(beta)) @ x @ W + bias
// R8->R9: keep 2 CTAs/SM (MT=32) but restore the single-barrier 3-stage
// B ring from R7 (R8's 2-stage ring needed a 2nd __syncthreads per iter ->
// issue fell to 9.2%). Also fix cp.async B store mapping: contiguous 16B
// per thread (was 64B-strided -> 4-way STS conflicts).
// ============================================================

#define NN 8192
#define FF 256
#define MT 32             // CTA M tile (kernel B)
#define KS 64             // K per stage
#define NITER (NN / KS)   // 128
#define KSPA 72           // A row stride in halves (144B)
#define KSPB 264          // B row stride in halves (528B): conflict-free ldm
#define AS_STAGE (MT * KSPA)        // 2304 halves
#define AS_STAGE_B (AS_STAGE * 2)   // 4608 B
#define BS_STAGE (KS * KSPB)        // 16896 halves
#define BS_STAGE_B (BS_STAGE * 2)   // 33792 B

#define OFF_BIAS  0      // 256 f32
#define OFF_RS    1024   // 32 f32
#define OFF_SCALE 1152
#define OFF_BETA  1280
#define OFF_AS    1536                        // 2 stages * 4608
#define OFF_BS    (OFF_AS + 2 * AS_STAGE_B)   // 10752, 3 stages * 33792
#define SMEM_TOTAL (OFF_BS + 3 * BS_STAGE_B)  // 112128 (x2 CTAs = 224256/SM)

__device__ __align__(256) float  g_y[NN * FF];   // y [node][feat] fp32
__device__ __align__(256) __half g_yh[NN * FF];  // y [node][feat] fp16 (row-major)

// ---------------- helpers ----------------
__device__ __forceinline__ uint32_t smem_u32(const void* p) {
    uint32_t a;
    asm("{ .reg .u64 t; cvta.to.shared.u64 t, %1; cvt.u32.u64 %0, t; }" : "=r"(a) : "l"(p));
    return a;
}
__device__ __forceinline__ void cp16(uint32_t dst, const void* src) {
    asm volatile("cp.async.cg.shared.global [%0], [%1], 16;" :: "r"(dst), "l"(src));
}
__device__ __forceinline__ void cp_commit() {
    asm volatile("cp.async.commit_group;" ::: "memory");
}
__device__ __forceinline__ void ldm_x4(uint32_t* r, uint32_t addr) {
    asm volatile("ldmatrix.sync.aligned.m8n8.x4.shared.b16 {%0,%1,%2,%3}, [%4];"
        : "=r"(r[0]), "=r"(r[1]), "=r"(r[2]), "=r"(r[3]) : "r"(addr));
}
__device__ __forceinline__ void ldm_x4_t(uint32_t* r, uint32_t addr) {
    asm volatile("ldmatrix.sync.aligned.m8n8.x4.trans.shared.b16 {%0,%1,%2,%3}, [%4];"
        : "=r"(r[0]), "=r"(r[1]), "=r"(r[2]), "=r"(r[3]) : "r"(addr));
}
__device__ __forceinline__ void mma_f16(float* c, const uint32_t* a, uint32_t b0, uint32_t b1) {
    asm volatile(
        "mma.sync.aligned.m16n8k16.row.col.f32.f16.f16.f32 "
        "{%0,%1,%2,%3}, {%4,%5,%6,%7}, {%8,%9}, {%0,%1,%2,%3};"
        : "+f"(c[0]), "+f"(c[1]), "+f"(c[2]), "+f"(c[3])
        : "r"(a[0]), "r"(a[1]), "r"(a[2]), "r"(a[3]), "r"(b0), "r"(b1));
}

// ---------------- kernel A: y = x @ W (fp16 HMMA), writes g_y + g_yh ----------------
__global__ void __launch_bounds__(512) gemm_y_kernel(const float* __restrict__ x,
                                                     const float* __restrict__ w)
{
    __shared__ __half xs[64 * KSPA];    // [m][k] chunk
    __shared__ __half ws[64 * KSPB];    // [k][n] chunk (trans-ldm as B)
    const int tid = threadIdx.x;
    const int wid = tid >> 5, lane = tid & 31;
    const int g = lane >> 2, t = lane & 3;
    const int wm = wid & 1, wn = wid >> 1;
    const int m0 = blockIdx.x * 64;
    const int mt8 = lane >> 3, r8 = lane & 7;

    const uint32_t a_lm = smem_u32(xs) +
        (((wm * 32 + (mt8 & 1) * 8 + r8) * KSPA + (mt8 >> 1) * 8) * 2);
    const uint32_t b_lm = smem_u32(ws) +
        (((r8 + (mt8 & 1) * 8) * KSPB + wn * 32 + (lane >> 4) * 8) * 2);

    float acc[2][4][4];
    #pragma unroll
    for (int i = 0; i < 2; i++)
        #pragma unroll
        for (int j = 0; j < 4; j++)
            #pragma unroll
            for (int q = 0; q < 4; q++) acc[i][j][q] = 0.f;

    const int xr = tid >> 3, xq = tid & 7;       // x: row, 8-float chunk
    for (int c = 0; c < 4; c++) {
        const int k0 = c * 64;
        {   // stage x chunk [64m][64k] fp32 -> fp16
            const float4 v0 = *(const float4*)&x[(size_t)(m0 + xr) * FF + k0 + xq * 8];
            const float4 v1 = *(const float4*)&x[(size_t)(m0 + xr) * FF + k0 + xq * 8 + 4];
            __half2 h[4];
            h[0] = __floats2half2_rn(v0.x, v0.y); h[1] = __floats2half2_rn(v0.z, v0.w);
            h[2] = __floats2half2_rn(v1.x, v1.y); h[3] = __floats2half2_rn(v1.z, v1.w);
            *(uint4*)&xs[xr * KSPA + xq * 8] = make_uint4(
                *(uint32_t*)&h[0], *(uint32_t*)&h[1], *(uint32_t*)&h[2], *(uint32_t*)&h[3]);
        }
        {   // stage W chunk [64k][256n] fp32 -> fp16
            #pragma unroll
            for (int j2 = 0; j2 < 4; j2++) {
                const float4 u0 = *(const float4*)&w[(size_t)(k0 + xr) * FF + xq * 32 + j2 * 8];
                const float4 u1 = *(const float4*)&w[(size_t)(k0 + xr) * FF + xq * 32 + j2 * 8 + 4];
                __half2 h[4];
                h[0] = __floats2half2_rn(u0.x, u0.y); h[1] = __floats2half2_rn(u0.z, u0.w);
                h[2] = __floats2half2_rn(u1.x, u1.y); h[3] = __floats2half2_rn(u1.z, u1.w);
                *(uint4*)&ws[xr * KSPB + xq * 32 + j2 * 8] = make_uint4(
                    *(uint32_t*)&h[0], *(uint32_t*)&h[1], *(uint32_t*)&h[2], *(uint32_t*)&h[3]);
            }
        }
        __syncthreads();
        #pragma unroll
        for (int kk = 0; kk < 4; kk++) {
            uint32_t a0[4], a1[4];
            ldm_x4(a0, a_lm + kk * 32);
            ldm_x4(a1, a_lm + kk * 32 + 16 * KSPA * 2);
            uint32_t bf[2][4];
            #pragma unroll
            for (int p = 0; p < 2; p++)
                ldm_x4_t(bf[p], b_lm + (uint32_t)(kk * 16 * KSPB + p * 16) * 2);
            #pragma unroll
            for (int p = 0; p < 2; p++) {
                mma_f16(acc[0][2 * p],     a0, bf[p][0], bf[p][1]);
                mma_f16(acc[1][2 * p],     a1, bf[p][0], bf[p][1]);
                mma_f16(acc[0][2 * p + 1], a0, bf[p][2], bf[p][3]);
                mma_f16(acc[1][2 * p + 1], a1, bf[p][2], bf[p][3]);
            }
        }
        __syncthreads();
    }

    // epilogue: write fp32 g_y and fp16 g_yh (both row-major [m][n])
    #pragma unroll
    for (int mi = 0; mi < 2; mi++) {
        const int lm = wm * 32 + mi * 16 + g;
        #pragma unroll
        for (int nj = 0; nj < 4; nj++) {
            const int n = wn * 32 + nj * 8 + 2 * t;
            const float* cc = acc[mi][nj];
            const size_t b0 = (size_t)(m0 + lm) * FF + n;
            const size_t b1 = (size_t)(m0 + lm + 8) * FF + n;
            *(float2*)&g_y[b0] = make_float2(cc[0], cc[1]);
            *(float2*)&g_y[b1] = make_float2(cc[2], cc[3]);
            __half2 h0 = __floats2half2_rn(cc[0], cc[1]);
            __half2 h1 = __floats2half2_rn(cc[2], cc[3]);
            *(__half2*)&g_yh[b0] = h0;
            *(__half2*)&g_yh[b1] = h1;
        }
    }
}

// ---------------- kernel B: C = adj @ y + fused epilogue ----------------
__global__ void __launch_bounds__(512, 2) gcn_mma_kernel(
    const float* __restrict__ adj,
    const float* __restrict__ beta,
    const float* __restrict__ bias,
    float* __restrict__ out)
{
    extern __shared__ char smem[];
    float* bias_s  = (float*)(smem + OFF_BIAS);
    float* rs_s    = (float*)(smem + OFF_RS);
    float* scale_s = (float*)(smem + OFF_SCALE);
    float* beta_s  = (float*)(smem + OFF_BETA);
    __half* As     = (__half*)(smem + OFF_AS);
    const uint32_t sb = smem_u32(smem);

    const int tid = threadIdx.x;
    const int wid = tid >> 5, lane = tid & 31;
    const int g = lane >> 2, t = lane & 3;
    const int wm = wid & 1, wn = wid >> 1;     // 2 m-warps x 8 n-warps (tile 16x32)
    const int m0 = blockIdx.x * MT;

    if (tid < FF) bias_s[tid] = bias[tid];

    // A: 16 threads per row, 4 floats each
    const int ar = tid >> 4, acq = tid & 15;
    const float* aptr = adj + (size_t)(m0 + ar) * NN + acq * 4;
    __half* const a_st = As + ar * KSPA + acq * 4;      // generic ptr for STS
    // B: row-major g_yh[k][n]; 32 threads per k-row, contiguous 16B each,
    // 16 rows per pass, 4 passes per stage (KS=64 rows)
    const int br = tid >> 5, bq = tid & 31;
    const __half* bptr = g_yh + (size_t)br * FF + bq * 8;
    const uint32_t b_dst = sb + OFF_BS + (br * KSPB) * 2 + bq * 16;

    // ldmatrix lane addresses
    const int mt8 = lane >> 3, r8 = lane & 7;
    const uint32_t a_lm = sb + OFF_AS +
        (((wm * 16 + (mt8 & 1) * 8 + r8) * KSPA + (mt8 >> 1) * 8) * 2);
    const uint32_t b_lm = sb + OFF_BS +
        (((r8 + (mt8 & 1) * 8) * KSPB + wn * 32 + (lane >> 4) * 8) * 2);

    float rs_local = 0.f;
    float acc[4][4];
    #pragma unroll
    for (int j = 0; j < 4; j++)
        #pragma unroll
        for (int q = 0; q < 4; q++) acc[j][q] = 0.f;

    float4 ra[2];

    // ---- prologue: B stages 0,1 via cp.async; A stages 0,1 via LDG ----
    #pragma unroll
    for (int s = 0; s < 2; s++) {
        #pragma unroll
        for (int c = 0; c < 4; c++)
            cp16(b_dst + s * BS_STAGE_B + c * (16 * KSPB * 2),
                 (const void*)(bptr + ((size_t)s * KS + c * 16) * FF));
        cp_commit();
    }
    ra[0] = *(const float4*)(aptr);
    ra[1] = *(const float4*)(aptr + KS);
    {   // STS A stage 0 + rowsum
        const float4 v = ra[0];
        rs_local += v.x + v.y + v.z + v.w;
        __half2 h0 = __floats2half2_rn(v.x, v.y), h1 = __floats2half2_rn(v.z, v.w);
        *(uint2*)a_st = make_uint2(*(uint32_t*)&h0, *(uint32_t*)&h1);
    }

    // ---- main loop (single barrier per iter, 3-stage B ring) ----
    for (int i = 0; i < NITER; i++) {
        const int bbuf = i % 3;

        // LDG A stage i+2 into ra[i&1] (stage i regs already flushed)
        if (i + 2 < NITER)
            ra[i & 1] = *(const float4*)(aptr + (size_t)(i + 2) * KS);

        if (i < NITER - 1) { asm volatile("cp.async.wait_group 1;" ::: "memory"); }
        else               { asm volatile("cp.async.wait_group 0;" ::: "memory"); }
        __syncthreads();   // stage i visible; everyone done with stage i-1 bufs

        // STS A stage i+1 (regs loaded at iter i-1) + rowsum
        if (i + 1 < NITER) {
            const float4 v = ra[(i + 1) & 1];
            rs_local += v.x + v.y + v.z + v.w;
            __half2 h0 = __floats2half2_rn(v.x, v.y), h1 = __floats2half2_rn(v.z, v.w);
            *(uint2*)(a_st + ((i + 1) & 1) * AS_STAGE) =
                make_uint2(*(uint32_t*)&h0, *(uint32_t*)&h1);
        }
        // cp.async B stage i+2 into buf (i+2)%3 (free: compute i-1 done)
        if (i + 2 < NITER) {
            const uint32_t bd = b_dst + ((i + 2) % 3) * BS_STAGE_B;
            const __half* bp = bptr + (size_t)(i + 2) * KS * FF;
            #pragma unroll
            for (int c = 0; c < 4; c++)
                cp16(bd + c * (16 * KSPB * 2), (const void*)(bp + (size_t)c * 16 * FF));
            cp_commit();
        }

        // ---- compute stage i ----
        const uint32_t aB = a_lm + (i & 1) * AS_STAGE_B;
        const uint32_t bB = b_lm + bbuf * BS_STAGE_B;
        #pragma unroll
        for (int kk = 0; kk < 4; kk++) {
            uint32_t a[4];
            ldm_x4(a, aB + kk * 32);
            uint32_t bf0[4], bf1[4];
            ldm_x4_t(bf0, bB + (uint32_t)(kk * 16 * KSPB) * 2);
            ldm_x4_t(bf1, bB + (uint32_t)(kk * 16 * KSPB) * 2 + 32);
            mma_f16(acc[0], a, bf0[0], bf0[1]);
            mma_f16(acc[1], a, bf0[2], bf0[3]);
            mma_f16(acc[2], a, bf1[0], bf1[1]);
            mma_f16(acc[3], a, bf1[2], bf1[3]);
        }
    }

    // ---- rowsum reduce (16 threads per row) ----
    float rs = rs_local;
    rs += __shfl_xor_sync(0xffffffffu, rs, 1);
    rs += __shfl_xor_sync(0xffffffffu, rs, 2);
    rs += __shfl_xor_sync(0xffffffffu, rs, 4);
    rs += __shfl_xor_sync(0xffffffffu, rs, 8);
    if ((tid & 15) == 0) rs_s[ar] = rs;
    __syncthreads();
    if (tid < MT) {
        const float be = beta[m0 + tid];
        beta_s[tid] = be;
        scale_s[tid] = 1.0f / (rs_s[tid] + be);
    }
    __syncthreads();

    // ---- epilogue: out = scale*(C + beta*y) + bias ----
    const int lm = wm * 16 + g;
    const float sc0 = scale_s[lm],     be0 = beta_s[lm];
    const float sc1 = scale_s[lm + 8], be1 = beta_s[lm + 8];
    #pragma unroll
    for (int nj = 0; nj < 4; nj++) {
        const int n = wn * 32 + nj * 8 + 2 * t;
        const size_t base0 = (size_t)(m0 + lm) * FF + n;
        const size_t base1 = (size_t)(m0 + lm + 8) * FF + n;
        const float2 y0 = *(const float2*)&g_y[base0];
        const float2 y1 = *(const float2*)&g_y[base1];
        float2 o0, o1;
        o0.x = sc0 * (acc[nj][0] + be0 * y0.x) + bias_s[n];
        o0.y = sc0 * (acc[nj][1] + be0 * y0.y) + bias_s[n + 1];
        o1.x = sc1 * (acc[nj][2] + be1 * y1.x) + bias_s[n];
        o1.y = sc1 * (acc[nj][3] + be1 * y1.y) + bias_s[n + 1];
        *(float2*)&out[base0] = o0;
        *(float2*)&out[base1] = o1;
    }
}

// ---------------- launch ----------------
extern "C" void kernel_launch(void* const* d_in, const int* in_sizes, int n_in,
                              void* d_out, int out_size)
{
    const float *x = nullptr, *adj = nullptr, *w = nullptr, *bias = nullptr, *beta = nullptr;
    for (int i = 0; i < n_in; i++) {
        switch (in_sizes[i]) {
            case NN * FF:   x    = (const float*)d_in[i]; break;
            case 67108864:  adj  = (const float*)d_in[i]; break;
            case FF * FF:   w    = (const float*)d_in[i]; break;
            case FF:        bias = (const float*)d_in[i]; break;
            case NN:        beta = (const float*)d_in[i]; break;
            default: break;
        }
    }
    float* out = (float*)d_out;

    cudaFuncSetAttribute(gcn_mma_kernel, cudaFuncAttributeMaxDynamicSharedMemorySize, SMEM_TOTAL);

    gemm_y_kernel<<<NN / 64, 512>>>(x, w);
    gcn_mma_kernel<<<NN / MT, 512, SMEM_TOTAL>>>(adj, beta, bias, out);
}